// round 2
// baseline (speedup 1.0000x reference)
#include <cuda_runtime.h>

#define N_NODES 50000
#define N_EDGES 400000
#define IN_C 32
#define OUT_C 32
#define EDGE_DIM 16
#define HIDDEN 128
#define BN_EPS 1e-5f

#define A_COLS (HIDDEN * IN_C)   // 4096
#define SCAN_BLOCKS ((N_NODES + 255) / 256)  // 196
#define BN_BLOCKS 232

// ---------------- static device scratch (no allocations allowed) ------------
__device__ float g_H[(size_t)N_EDGES * HIDDEN];        // 205 MB
__device__ float g_A[(size_t)N_NODES * A_COLS];        // 819 MB
__device__ float g_xsum[(size_t)N_NODES * IN_C];
__device__ float g_h[(size_t)N_NODES * OUT_C];
__device__ int   g_hist[N_NODES];
__device__ int   g_off[N_NODES + 1];
__device__ int   g_cursor[N_NODES];
__device__ int   g_perm[N_EDGES];
__device__ int   g_bsum[256];
__device__ int   g_boff[256];
__device__ double g_psum[BN_BLOCKS][OUT_C];
__device__ double g_psq[BN_BLOCKS][OUT_C];
__device__ float g_scale[OUT_C];
__device__ float g_shift[OUT_C];
__device__ int   g_is64;

// ---------------- edge_index dtype detection ---------------------------------
// If the buffer holds int64 little-endian values < 2^31, every odd int32 word
// is zero. If it holds int32 indices, odd words are random indices (nonzero
// w.h.p.). 512 consecutive zero odd-words => int64.
__global__ void k_detect(const void* ei) {
    if (threadIdx.x == 0 && blockIdx.x == 0) {
        const int* p = (const int*)ei;
        int is64 = 1;
        for (int i = 0; i < 512; i++)
            if (p[2 * i + 1] != 0) { is64 = 0; break; }
        g_is64 = is64;
    }
}

__device__ __forceinline__ int load_idx(const void* ei, int is64, long long elem) {
    int v = is64 ? (int)((const long long*)ei)[elem] : ((const int*)ei)[elem];
    // clamp: pure safety net, no-op for valid data
    return min(max(v, 0), N_NODES - 1);
}

// ---------------- init ------------------------------------------------------
__global__ void k_init() {
    for (int i = blockIdx.x * blockDim.x + threadIdx.x; i < N_NODES;
         i += gridDim.x * blockDim.x)
        g_hist[i] = 0;
}

// ---------------- histogram over dst ----------------------------------------
__global__ void k_hist(const void* __restrict__ ei) {
    int is64 = g_is64;
    for (int i = blockIdx.x * blockDim.x + threadIdx.x; i < N_EDGES;
         i += gridDim.x * blockDim.x) {
        int dst = load_idx(ei, is64, (long long)N_EDGES + i);
        atomicAdd(&g_hist[dst], 1);
    }
}

// ---------------- 3-kernel exclusive scan (256/block) -----------------------
__device__ __forceinline__ int block_excl_scan256(int v) {
    int tid = threadIdx.x;
    int lane = tid & 31, wid = tid >> 5;
    int incl = v;
#pragma unroll
    for (int o = 1; o < 32; o <<= 1) {
        int nv = __shfl_up_sync(0xffffffffu, incl, o);
        if (lane >= o) incl += nv;
    }
    __shared__ int ws[8];
    if (lane == 31) ws[wid] = incl;
    __syncthreads();
    if (wid == 0) {
        int wv = (lane < 8) ? ws[lane] : 0;
#pragma unroll
        for (int o = 1; o < 8; o <<= 1) {
            int nv = __shfl_up_sync(0xffffffffu, wv, o);
            if (lane >= o) wv += nv;
        }
        if (lane < 8) ws[lane] = wv;
    }
    __syncthreads();
    int base = (wid > 0) ? ws[wid - 1] : 0;
    return base + incl - v;
}

__global__ void k_scan_a() {
    int idx = blockIdx.x * 256 + threadIdx.x;
    int v = (idx < N_NODES) ? g_hist[idx] : 0;
    int ex = block_excl_scan256(v);
    if (threadIdx.x == 255) g_bsum[blockIdx.x] = ex + v;
}

__global__ void k_scan_b() {
    int tid = threadIdx.x;
    int v = (tid < SCAN_BLOCKS) ? g_bsum[tid] : 0;
    int ex = block_excl_scan256(v);
    if (tid < SCAN_BLOCKS) g_boff[tid] = ex;
    if (tid == 0) g_off[N_NODES] = N_EDGES;
}

__global__ void k_scan_c() {
    int idx = blockIdx.x * 256 + threadIdx.x;
    int v = (idx < N_NODES) ? g_hist[idx] : 0;
    int ex = block_excl_scan256(v) + g_boff[blockIdx.x];
    if (idx < N_NODES) {
        g_off[idx] = ex;
        g_cursor[idx] = ex;
    }
}

// ---------------- scatter edge ids grouped by dst ---------------------------
__global__ void k_scatter(const void* __restrict__ ei) {
    int is64 = g_is64;
    for (int i = blockIdx.x * blockDim.x + threadIdx.x; i < N_EDGES;
         i += gridDim.x * blockDim.x) {
        int dst = load_idx(ei, is64, (long long)N_EDGES + i);
        int pos = atomicAdd(&g_cursor[dst], 1);
        g_perm[pos] = i;
    }
}

// ---------------- edge MLP layer 1: H = relu(EA @ W1 + b1) ------------------
// block: 128 threads (one hidden unit per thread), 32 edges per block.
__global__ void __launch_bounds__(128) k_edgemlp(const float* __restrict__ ea,
                                                 const float* __restrict__ w1,
                                                 const float* __restrict__ b1) {
    int tid = threadIdx.x;
    float w1r[EDGE_DIM];
#pragma unroll
    for (int k = 0; k < EDGE_DIM; k++) w1r[k] = w1[k * HIDDEN + tid];
    float b1v = b1[tid];

    __shared__ float4 eas[32][4];
    int e0 = blockIdx.x * 32;
    {
        int j = tid >> 2, q = tid & 3;
        eas[j][q] = ((const float4*)(ea + (size_t)(e0 + j) * EDGE_DIM))[q];
    }
    __syncthreads();

#pragma unroll 4
    for (int j = 0; j < 32; j++) {
        float4 a0 = eas[j][0], a1 = eas[j][1], a2 = eas[j][2], a3 = eas[j][3];
        float acc = b1v;
        acc += a0.x * w1r[0] + a0.y * w1r[1] + a0.z * w1r[2] + a0.w * w1r[3];
        acc += a1.x * w1r[4] + a1.y * w1r[5] + a1.z * w1r[6] + a1.w * w1r[7];
        acc += a2.x * w1r[8] + a2.y * w1r[9] + a2.z * w1r[10] + a2.w * w1r[11];
        acc += a3.x * w1r[12] + a3.y * w1r[13] + a3.z * w1r[14] + a3.w * w1r[15];
        g_H[(size_t)(e0 + j) * HIDDEN + tid] = fmaxf(acc, 0.f);
    }
}

// ---------------- A build: per-dst rank-1 accumulation ----------------------
// block = one node, 128 threads (one h per thread), acc over its in-edges.
__global__ void __launch_bounds__(128) k_abuild(const float* __restrict__ x,
                                                const void* __restrict__ ei) {
    int n = blockIdx.x;
    int tid = threadIdx.x;
    int is64 = g_is64;
    int start = g_off[n], end = g_off[n + 1];

    float acc[IN_C];
#pragma unroll
    for (int i = 0; i < IN_C; i++) acc[i] = 0.f;
    float xs = 0.f;

    for (int j = start; j < end; j++) {
        int e = g_perm[j];
        int src = load_idx(ei, is64, e);
        const float4* xp = (const float4*)(x + (size_t)src * IN_C);
        float he = g_H[(size_t)e * HIDDEN + tid];
#pragma unroll
        for (int q = 0; q < 8; q++) {
            float4 v = xp[q];
            acc[4 * q + 0] += he * v.x;
            acc[4 * q + 1] += he * v.y;
            acc[4 * q + 2] += he * v.z;
            acc[4 * q + 3] += he * v.w;
        }
        if (tid < IN_C) xs += x[(size_t)src * IN_C + tid];
    }

    float4* ap = (float4*)(g_A + (size_t)n * A_COLS + tid * IN_C);
#pragma unroll
    for (int q = 0; q < 8; q++)
        ap[q] = make_float4(acc[4 * q + 0], acc[4 * q + 1], acc[4 * q + 2],
                            acc[4 * q + 3]);
    if (tid < IN_C) g_xsum[n * IN_C + tid] = xs;
}

// ---------------- main GEMM: h = (A@W2r + xsum@B2r)/cnt + x@rootW + bias ----
// tile: 128 rows x 32 cols, K=4096 in 32-wide tiles. 256 threads,
// each thread: 8 rows x 2 cols = 16 accumulators.
__global__ void __launch_bounds__(256) k_gemm(const float* __restrict__ x,
                                              const float* __restrict__ w2,
                                              const float* __restrict__ b2,
                                              const float* __restrict__ rw,
                                              const float* __restrict__ cb) {
    __shared__ float A_s[128 * 32];
    __shared__ float W_sT[32 * 36];   // [o][i], padded stride 36
    __shared__ float B2s[1024];
    __shared__ float RWs[1024];
    __shared__ float cbs[32];

    int tid = threadIdx.x;
    int rowbase = blockIdx.x * 128;

#pragma unroll
    for (int q = 0; q < 4; q++) {
        int id = tid + q * 256;
        B2s[id] = b2[id];
        RWs[id] = rw[id];
    }
    if (tid < 32) cbs[tid] = cb[tid];

    float acc0[8], acc1[8];
#pragma unroll
    for (int r = 0; r < 8; r++) { acc0[r] = 0.f; acc1[r] = 0.f; }

    int tx = tid & 15, ty = tid >> 4;
    int rr = tid >> 1, hf = tid & 1;
    bool rowok = (rowbase + rr) < N_NODES;
    const float4* asrc =
        (const float4*)(g_A + (size_t)(rowbase + rr) * A_COLS + hf * 16);
    float4* adst = (float4*)(&A_s[rr * 32 + hf * 16]);

    for (int kt = 0; kt < 128; kt++) {
        // stage A tile (128 rows x 32 k)
#pragma unroll
        for (int q = 0; q < 4; q++) {
            float4 v = rowok ? asrc[(size_t)kt * 8 + q] : make_float4(0, 0, 0, 0);
            adst[q] = v;
        }
        // stage W tile transposed: W_sT[o][i] = w2[kt*1024 + i*32 + o]
#pragma unroll
        for (int q = 0; q < 4; q++) {
            int id = tid + q * 256;
            int i = id >> 5, o = id & 31;
            W_sT[o * 36 + i] = w2[(size_t)kt * 1024 + id];
        }
        __syncthreads();

#pragma unroll
        for (int kk4 = 0; kk4 < 8; kk4++) {
            float4 wf0 = *(const float4*)&W_sT[tx * 36 + kk4 * 4];
            float4 wf1 = *(const float4*)&W_sT[(tx + 16) * 36 + kk4 * 4];
#pragma unroll
            for (int r = 0; r < 8; r++) {
                float4 af = *(const float4*)&A_s[(ty + (r << 4)) * 32 + kk4 * 4];
                acc0[r] += af.x * wf0.x; acc0[r] += af.y * wf0.y;
                acc0[r] += af.z * wf0.z; acc0[r] += af.w * wf0.w;
                acc1[r] += af.x * wf1.x; acc1[r] += af.y * wf1.y;
                acc1[r] += af.z * wf1.z; acc1[r] += af.w * wf1.w;
            }
        }
        __syncthreads();
    }

    // epilogue: mean, b2 term, root term, conv bias
#pragma unroll
    for (int r = 0; r < 8; r++) {
        int mg = rowbase + ty + (r << 4);
        if (mg < N_NODES) {
            float cnt = (float)(g_off[mg + 1] - g_off[mg]);
            float inv = 1.f / fmaxf(cnt, 1.f);
            const float* xsp = g_xsum + (size_t)mg * IN_C;
            const float* xp = x + (size_t)mg * IN_C;
            float e0 = 0.f, e1 = 0.f, r0 = 0.f, r1 = 0.f;
#pragma unroll
            for (int i = 0; i < IN_C; i++) {
                float sv = xsp[i], xv = xp[i];
                e0 += sv * B2s[i * 32 + tx];
                e1 += sv * B2s[i * 32 + tx + 16];
                r0 += xv * RWs[i * 32 + tx];
                r1 += xv * RWs[i * 32 + tx + 16];
            }
            g_h[(size_t)mg * 32 + tx] = (acc0[r] + e0) * inv + r0 + cbs[tx];
            g_h[(size_t)mg * 32 + tx + 16] =
                (acc1[r] + e1) * inv + r1 + cbs[tx + 16];
        }
    }
}

// ---------------- BatchNorm statistics (deterministic, no atomics) ----------
__global__ void k_bnstats() {
    int tid = threadIdx.x;  // 256
    int c = tid & 31, g = tid >> 5;
    double s = 0.0, s2 = 0.0;
    for (int row = blockIdx.x * 8 + g; row < N_NODES; row += gridDim.x * 8) {
        float v = g_h[(size_t)row * 32 + c];
        s += (double)v;
        s2 += (double)v * (double)v;
    }
    __shared__ double sh[256], sh2[256];
    sh[tid] = s; sh2[tid] = s2;
    __syncthreads();
    for (int off = 128; off >= 32; off >>= 1) {
        if (tid < off) { sh[tid] += sh[tid + off]; sh2[tid] += sh2[tid + off]; }
        __syncthreads();
    }
    if (tid < 32) {
        g_psum[blockIdx.x][tid] = sh[tid];
        g_psq[blockIdx.x][tid] = sh2[tid];
    }
}

__global__ void k_bnfin(const float* __restrict__ gamma,
                        const float* __restrict__ beta) {
    int c = threadIdx.x;
    if (c < OUT_C) {
        double s = 0.0, s2 = 0.0;
        for (int b = 0; b < BN_BLOCKS; b++) {
            s += g_psum[b][c];
            s2 += g_psq[b][c];
        }
        double mu = s / (double)N_NODES;
        double var = s2 / (double)N_NODES - mu * mu;
        float rstd = (float)rsqrt(var + (double)BN_EPS);
        float sc = rstd * gamma[c];
        g_scale[c] = sc;
        g_shift[c] = beta[c] - (float)mu * sc;
    }
}

// ---------------- output: x + relu(BN(h)) ------------------------------------
__global__ void k_out(const float* __restrict__ x, float* __restrict__ out) {
    int i = blockIdx.x * blockDim.x + threadIdx.x;
    const int total = N_NODES * OUT_C / 4;
    if (i < total) {
        float4 xv = ((const float4*)x)[i];
        float4 hv = ((const float4*)g_h)[i];
        int c = (i & 7) * 4;
        float4 o;
        o.x = xv.x + fmaxf(hv.x * g_scale[c + 0] + g_shift[c + 0], 0.f);
        o.y = xv.y + fmaxf(hv.y * g_scale[c + 1] + g_shift[c + 1], 0.f);
        o.z = xv.z + fmaxf(hv.z * g_scale[c + 2] + g_shift[c + 2], 0.f);
        o.w = xv.w + fmaxf(hv.w * g_scale[c + 3] + g_shift[c + 3], 0.f);
        ((float4*)out)[i] = o;
    }
}

// ---------------- launch -----------------------------------------------------
extern "C" void kernel_launch(void* const* d_in, const int* in_sizes, int n_in,
                              void* d_out, int out_size) {
    const float* x   = (const float*)d_in[0];
    const void*  ei  = d_in[1];               // int32 or int64, detected on device
    const float* ea  = (const float*)d_in[2];
    const float* w1  = (const float*)d_in[3];
    const float* b1  = (const float*)d_in[4];
    const float* w2  = (const float*)d_in[5];
    const float* b2  = (const float*)d_in[6];
    const float* rw  = (const float*)d_in[7];
    const float* cb  = (const float*)d_in[8];
    const float* gam = (const float*)d_in[9];
    const float* bet = (const float*)d_in[10];
    float* out = (float*)d_out;

    k_detect<<<1, 32>>>(ei);
    k_init<<<196, 256>>>();
    k_hist<<<512, 256>>>(ei);
    k_scan_a<<<SCAN_BLOCKS, 256>>>();
    k_scan_b<<<1, 256>>>();
    k_scan_c<<<SCAN_BLOCKS, 256>>>();
    k_scatter<<<512, 256>>>(ei);
    k_edgemlp<<<N_EDGES / 32, 128>>>(ea, w1, b1);
    k_abuild<<<N_NODES, 128>>>(x, ei);
    k_gemm<<<(N_NODES + 127) / 128, 256>>>(x, w2, b2, rw, cb);
    k_bnstats<<<BN_BLOCKS, 256>>>();
    k_bnfin<<<1, 32>>>(gam, bet);
    k_out<<<(N_NODES * OUT_C / 4 + 255) / 256, 256>>>(x, out);
}

// round 3
// speedup vs baseline: 1.2347x; 1.2347x over previous
#include <cuda_runtime.h>
#include <cuda_bf16.h>
#include <cstdint>

#define N_NODES 50000
#define N_EDGES 400000
#define IN_C 32
#define OUT_C 32
#define EDGE_DIM 16
#define HIDDEN 128
#define BN_EPS 1e-5f

#define A_COLS (HIDDEN * IN_C)   // 4096
#define SCAN_BLOCKS ((N_NODES + 255) / 256)  // 196
#define BN_BLOCKS 232

// GEMM tiling
#define BM 128
#define BK 32
#define ASTR 40   // bf16 row stride (pad 32 -> 40: conflict-free frag loads)
#define WSTR 40

// ---------------- static device scratch (no allocations allowed) ------------
__device__ float g_H[(size_t)N_EDGES * HIDDEN];        // 205 MB
__device__ float g_A[(size_t)N_NODES * A_COLS];        // 819 MB
__device__ float g_xsum[(size_t)N_NODES * IN_C];
__device__ float g_h[(size_t)N_NODES * OUT_C];
__device__ int   g_hist[N_NODES];
__device__ int   g_off[N_NODES + 1];
__device__ int   g_cursor[N_NODES];
__device__ int   g_perm[N_EDGES];
__device__ int   g_bsum[256];
__device__ int   g_boff[256];
__device__ double g_psum[BN_BLOCKS][OUT_C];
__device__ double g_psq[BN_BLOCKS][OUT_C];
__device__ float g_scale[OUT_C];
__device__ float g_shift[OUT_C];
__device__ int   g_is64;

// ---------------- edge_index dtype detection ---------------------------------
__global__ void k_detect(const void* ei) {
    if (threadIdx.x == 0 && blockIdx.x == 0) {
        const int* p = (const int*)ei;
        int is64 = 1;
        for (int i = 0; i < 512; i++)
            if (p[2 * i + 1] != 0) { is64 = 0; break; }
        g_is64 = is64;
    }
}

__device__ __forceinline__ int load_idx(const void* ei, int is64, long long elem) {
    int v = is64 ? (int)((const long long*)ei)[elem] : ((const int*)ei)[elem];
    return min(max(v, 0), N_NODES - 1);
}

// ---------------- init ------------------------------------------------------
__global__ void k_init() {
    for (int i = blockIdx.x * blockDim.x + threadIdx.x; i < N_NODES;
         i += gridDim.x * blockDim.x)
        g_hist[i] = 0;
}

// ---------------- histogram over dst ----------------------------------------
__global__ void k_hist(const void* __restrict__ ei) {
    int is64 = g_is64;
    for (int i = blockIdx.x * blockDim.x + threadIdx.x; i < N_EDGES;
         i += gridDim.x * blockDim.x) {
        int dst = load_idx(ei, is64, (long long)N_EDGES + i);
        atomicAdd(&g_hist[dst], 1);
    }
}

// ---------------- 3-kernel exclusive scan (256/block) -----------------------
__device__ __forceinline__ int block_excl_scan256(int v) {
    int tid = threadIdx.x;
    int lane = tid & 31, wid = tid >> 5;
    int incl = v;
#pragma unroll
    for (int o = 1; o < 32; o <<= 1) {
        int nv = __shfl_up_sync(0xffffffffu, incl, o);
        if (lane >= o) incl += nv;
    }
    __shared__ int ws[8];
    if (lane == 31) ws[wid] = incl;
    __syncthreads();
    if (wid == 0) {
        int wv = (lane < 8) ? ws[lane] : 0;
#pragma unroll
        for (int o = 1; o < 8; o <<= 1) {
            int nv = __shfl_up_sync(0xffffffffu, wv, o);
            if (lane >= o) wv += nv;
        }
        if (lane < 8) ws[lane] = wv;
    }
    __syncthreads();
    int base = (wid > 0) ? ws[wid - 1] : 0;
    return base + incl - v;
}

__global__ void k_scan_a() {
    int idx = blockIdx.x * 256 + threadIdx.x;
    int v = (idx < N_NODES) ? g_hist[idx] : 0;
    int ex = block_excl_scan256(v);
    if (threadIdx.x == 255) g_bsum[blockIdx.x] = ex + v;
}

__global__ void k_scan_b() {
    int tid = threadIdx.x;
    int v = (tid < SCAN_BLOCKS) ? g_bsum[tid] : 0;
    int ex = block_excl_scan256(v);
    if (tid < SCAN_BLOCKS) g_boff[tid] = ex;
    if (tid == 0) g_off[N_NODES] = N_EDGES;
}

__global__ void k_scan_c() {
    int idx = blockIdx.x * 256 + threadIdx.x;
    int v = (idx < N_NODES) ? g_hist[idx] : 0;
    int ex = block_excl_scan256(v) + g_boff[blockIdx.x];
    if (idx < N_NODES) {
        g_off[idx] = ex;
        g_cursor[idx] = ex;
    }
}

// ---------------- scatter edge ids grouped by dst ---------------------------
__global__ void k_scatter(const void* __restrict__ ei) {
    int is64 = g_is64;
    for (int i = blockIdx.x * blockDim.x + threadIdx.x; i < N_EDGES;
         i += gridDim.x * blockDim.x) {
        int dst = load_idx(ei, is64, (long long)N_EDGES + i);
        int pos = atomicAdd(&g_cursor[dst], 1);
        g_perm[pos] = i;
    }
}

// ---------------- edge MLP layer 1: H = relu(EA @ W1 + b1) ------------------
__global__ void __launch_bounds__(128) k_edgemlp(const float* __restrict__ ea,
                                                 const float* __restrict__ w1,
                                                 const float* __restrict__ b1) {
    int tid = threadIdx.x;
    float w1r[EDGE_DIM];
#pragma unroll
    for (int k = 0; k < EDGE_DIM; k++) w1r[k] = w1[k * HIDDEN + tid];
    float b1v = b1[tid];

    __shared__ float4 eas[32][4];
    int e0 = blockIdx.x * 32;
    {
        int j = tid >> 2, q = tid & 3;
        eas[j][q] = ((const float4*)(ea + (size_t)(e0 + j) * EDGE_DIM))[q];
    }
    __syncthreads();

#pragma unroll 4
    for (int j = 0; j < 32; j++) {
        float4 a0 = eas[j][0], a1 = eas[j][1], a2 = eas[j][2], a3 = eas[j][3];
        float acc = b1v;
        acc += a0.x * w1r[0] + a0.y * w1r[1] + a0.z * w1r[2] + a0.w * w1r[3];
        acc += a1.x * w1r[4] + a1.y * w1r[5] + a1.z * w1r[6] + a1.w * w1r[7];
        acc += a2.x * w1r[8] + a2.y * w1r[9] + a2.z * w1r[10] + a2.w * w1r[11];
        acc += a3.x * w1r[12] + a3.y * w1r[13] + a3.z * w1r[14] + a3.w * w1r[15];
        g_H[(size_t)(e0 + j) * HIDDEN + tid] = fmaxf(acc, 0.f);
    }
}

// ---------------- A build: per-dst rank-1 accumulation ----------------------
__global__ void __launch_bounds__(128) k_abuild(const float* __restrict__ x,
                                                const void* __restrict__ ei) {
    int n = blockIdx.x;
    int tid = threadIdx.x;
    int is64 = g_is64;
    int start = g_off[n], end = g_off[n + 1];

    float acc[IN_C];
#pragma unroll
    for (int i = 0; i < IN_C; i++) acc[i] = 0.f;
    float xs = 0.f;

    for (int j = start; j < end; j++) {
        int e = g_perm[j];
        int src = load_idx(ei, is64, e);
        const float4* xp = (const float4*)(x + (size_t)src * IN_C);
        float he = g_H[(size_t)e * HIDDEN + tid];
#pragma unroll
        for (int q = 0; q < 8; q++) {
            float4 v = xp[q];
            acc[4 * q + 0] += he * v.x;
            acc[4 * q + 1] += he * v.y;
            acc[4 * q + 2] += he * v.z;
            acc[4 * q + 3] += he * v.w;
        }
        if (tid < IN_C) xs += x[(size_t)src * IN_C + tid];
    }

    float4* ap = (float4*)(g_A + (size_t)n * A_COLS + tid * IN_C);
#pragma unroll
    for (int q = 0; q < 8; q++)
        ap[q] = make_float4(acc[4 * q + 0], acc[4 * q + 1], acc[4 * q + 2],
                            acc[4 * q + 3]);
    if (tid < IN_C) g_xsum[n * IN_C + tid] = xs;
}

// ---------------- helpers for split-bf16 MMA ---------------------------------
__device__ __forceinline__ void split_bf(float v, __nv_bfloat16& h,
                                         __nv_bfloat16& l) {
    h = __float2bfloat16_rn(v);
    l = __float2bfloat16_rn(v - __bfloat162float(h));
}

__device__ __forceinline__ uint32_t pack_bf(__nv_bfloat16 a, __nv_bfloat16 b) {
    __nv_bfloat162 p;
    p.x = a; p.y = b;
    return *reinterpret_cast<uint32_t*>(&p);
}

__device__ __forceinline__ uint32_t lds_u32(const __nv_bfloat16* p) {
    return *reinterpret_cast<const uint32_t*>(p);
}

__device__ __forceinline__ void mma16816(float c[4], uint32_t a0, uint32_t a1,
                                         uint32_t a2, uint32_t a3, uint32_t b0,
                                         uint32_t b1) {
    asm volatile(
        "mma.sync.aligned.m16n8k16.row.col.f32.bf16.bf16.f32 "
        "{%0,%1,%2,%3}, {%4,%5,%6,%7}, {%8,%9}, {%0,%1,%2,%3};"
        : "+f"(c[0]), "+f"(c[1]), "+f"(c[2]), "+f"(c[3])
        : "r"(a0), "r"(a1), "r"(a2), "r"(a3), "r"(b0), "r"(b1));
}

// ---------------- main GEMM on tensor cores (split bf16, 3 passes) ----------
// h = (A@W2r + xsum@B2r)/cnt + x@rootW + bias
__global__ void __launch_bounds__(256) k_gemm(const float* __restrict__ x,
                                              const float* __restrict__ w2,
                                              const float* __restrict__ b2,
                                              const float* __restrict__ rw,
                                              const float* __restrict__ cb) {
    __shared__ __align__(16) unsigned char SMEM[2 * BM * ASTR * 2 + 2 * 32 * WSTR * 2];
    __nv_bfloat16* A_hi = (__nv_bfloat16*)SMEM;                          // 10240 B
    __nv_bfloat16* A_lo = (__nv_bfloat16*)(SMEM + BM * ASTR * 2);        // 10240 B
    __nv_bfloat16* Wt_hi = (__nv_bfloat16*)(SMEM + 2 * BM * ASTR * 2);   // 2560 B
    __nv_bfloat16* Wt_lo = (__nv_bfloat16*)(SMEM + 2 * BM * ASTR * 2 + 32 * WSTR * 2);
    float* C_s = (float*)SMEM;  // 16 KB alias of A planes (used after mma)
    __shared__ float B2s[1024], RWs[1024], cbs[32];

    int tid = threadIdx.x;
    int warp = tid >> 5, lane = tid & 31;
    int gi = lane >> 2, tq = lane & 3;
    int rowbase = blockIdx.x * BM;

#pragma unroll
    for (int q = 0; q < 4; q++) {
        int id = tid + q * 256;
        B2s[id] = b2[id];
        RWs[id] = rw[id];
    }
    if (tid < 32) cbs[tid] = cb[tid];

    float c[4][4];
#pragma unroll
    for (int j = 0; j < 4; j++)
#pragma unroll
        for (int r = 0; r < 4; r++) c[j][r] = 0.f;

    int lrow = tid >> 1, half = tid & 1;
    bool rowok = (rowbase + lrow) < N_NODES;
    const float4* asrc = (const float4*)(g_A + (size_t)(rowbase + lrow) * A_COLS);

    for (int kt = 0; kt < A_COLS / BK; kt++) {
        // ---- stage A tile: 128 rows x 32 k, fp32 -> bf16 hi/lo ----
#pragma unroll
        for (int q = 0; q < 4; q++) {
            float4 v = rowok ? asrc[kt * 8 + half * 4 + q]
                             : make_float4(0.f, 0.f, 0.f, 0.f);
            int scol = half * 16 + q * 4;
            __nv_bfloat16 h0, h1, h2, h3, l0, l1, l2, l3;
            split_bf(v.x, h0, l0); split_bf(v.y, h1, l1);
            split_bf(v.z, h2, l2); split_bf(v.w, h3, l3);
            uint32_t* dh = (uint32_t*)&A_hi[lrow * ASTR + scol];
            uint32_t* dl = (uint32_t*)&A_lo[lrow * ASTR + scol];
            dh[0] = pack_bf(h0, h1); dh[1] = pack_bf(h2, h3);
            dl[0] = pack_bf(l0, l1); dl[1] = pack_bf(l2, l3);
        }
        // ---- stage W tile transposed: Wt[n][k], 32x32 ----
#pragma unroll
        for (int q = 0; q < 4; q++) {
            int id = tid + q * 256;
            int k = id >> 5, n = id & 31;
            float wv = w2[(size_t)(kt * BK + k) * 32 + n];
            __nv_bfloat16 wh, wl;
            split_bf(wv, wh, wl);
            Wt_hi[n * WSTR + k] = wh;
            Wt_lo[n * WSTR + k] = wl;
        }
        __syncthreads();

        // ---- mma: warp owns 16 rows, full N=32 ----
        int rb = warp * 16;
#pragma unroll
        for (int kk = 0; kk < BK; kk += 16) {
            const __nv_bfloat16* ah = &A_hi[(rb + gi) * ASTR + kk + 2 * tq];
            const __nv_bfloat16* al = &A_lo[(rb + gi) * ASTR + kk + 2 * tq];
            uint32_t a0h = lds_u32(ah), a1h = lds_u32(ah + 8 * ASTR);
            uint32_t a2h = lds_u32(ah + 8), a3h = lds_u32(ah + 8 * ASTR + 8);
            uint32_t a0l = lds_u32(al), a1l = lds_u32(al + 8 * ASTR);
            uint32_t a2l = lds_u32(al + 8), a3l = lds_u32(al + 8 * ASTR + 8);
#pragma unroll
            for (int j = 0; j < 4; j++) {
                const __nv_bfloat16* bh = &Wt_hi[(j * 8 + gi) * WSTR + kk + 2 * tq];
                const __nv_bfloat16* bl = &Wt_lo[(j * 8 + gi) * WSTR + kk + 2 * tq];
                uint32_t b0h = lds_u32(bh), b1h = lds_u32(bh + 8);
                uint32_t b0l = lds_u32(bl), b1l = lds_u32(bl + 8);
                mma16816(c[j], a0h, a1h, a2h, a3h, b0h, b1h);
                mma16816(c[j], a0h, a1h, a2h, a3h, b0l, b1l);
                mma16816(c[j], a0l, a1l, a2l, a3l, b0h, b1h);
            }
        }
        __syncthreads();
    }

    // ---- dump accumulators to shared (aliases A planes) ----
    {
        int rb = warp * 16;
#pragma unroll
        for (int j = 0; j < 4; j++) {
            int col = j * 8 + 2 * tq;
            C_s[(rb + gi) * 32 + col] = c[j][0];
            C_s[(rb + gi) * 32 + col + 1] = c[j][1];
            C_s[(rb + gi + 8) * 32 + col] = c[j][2];
            C_s[(rb + gi + 8) * 32 + col + 1] = c[j][3];
        }
    }
    __syncthreads();

    // ---- epilogue: mean, b2 term, root term, conv bias ----
    {
        int row = tid >> 1, ch = tid & 1;
        int mg = rowbase + row;
        if (mg < N_NODES) {
            float cnt = (float)(g_off[mg + 1] - g_off[mg]);
            float inv = 1.f / fmaxf(cnt, 1.f);
            const float4* xsp = (const float4*)(g_xsum + (size_t)mg * IN_C);
            const float4* xp = (const float4*)(x + (size_t)mg * IN_C);
            float eacc[16], racc[16];
#pragma unroll
            for (int cjj = 0; cjj < 16; cjj++) { eacc[cjj] = 0.f; racc[cjj] = 0.f; }
#pragma unroll
            for (int i4 = 0; i4 < 8; i4++) {
                float4 xs = xsp[i4];
                float4 xv = xp[i4];
                float sv[4] = {xs.x, xs.y, xs.z, xs.w};
                float vv[4] = {xv.x, xv.y, xv.z, xv.w};
#pragma unroll
                for (int ii = 0; ii < 4; ii++) {
                    int i = i4 * 4 + ii;
#pragma unroll
                    for (int cjj = 0; cjj < 16; cjj++) {
                        int col = ch * 16 + cjj;
                        eacc[cjj] += sv[ii] * B2s[i * 32 + col];
                        racc[cjj] += vv[ii] * RWs[i * 32 + col];
                    }
                }
            }
#pragma unroll
            for (int cjj = 0; cjj < 16; cjj++) {
                int col = ch * 16 + cjj;
                g_h[(size_t)mg * 32 + col] =
                    (C_s[row * 32 + col] + eacc[cjj]) * inv + racc[cjj] + cbs[col];
            }
        }
    }
}

// ---------------- BatchNorm statistics (deterministic, no atomics) ----------
__global__ void k_bnstats() {
    int tid = threadIdx.x;  // 256
    int c = tid & 31, g = tid >> 5;
    double s = 0.0, s2 = 0.0;
    for (int row = blockIdx.x * 8 + g; row < N_NODES; row += gridDim.x * 8) {
        float v = g_h[(size_t)row * 32 + c];
        s += (double)v;
        s2 += (double)v * (double)v;
    }
    __shared__ double sh[256], sh2[256];
    sh[tid] = s; sh2[tid] = s2;
    __syncthreads();
    for (int off = 128; off >= 32; off >>= 1) {
        if (tid < off) { sh[tid] += sh[tid + off]; sh2[tid] += sh2[tid + off]; }
        __syncthreads();
    }
    if (tid < 32) {
        g_psum[blockIdx.x][tid] = sh[tid];
        g_psq[blockIdx.x][tid] = sh2[tid];
    }
}

__global__ void k_bnfin(const float* __restrict__ gamma,
                        const float* __restrict__ beta) {
    int c = threadIdx.x;
    if (c < OUT_C) {
        double s = 0.0, s2 = 0.0;
        for (int b = 0; b < BN_BLOCKS; b++) {
            s += g_psum[b][c];
            s2 += g_psq[b][c];
        }
        double mu = s / (double)N_NODES;
        double var = s2 / (double)N_NODES - mu * mu;
        float rstd = (float)rsqrt(var + (double)BN_EPS);
        float sc = rstd * gamma[c];
        g_scale[c] = sc;
        g_shift[c] = beta[c] - (float)mu * sc;
    }
}

// ---------------- output: x + relu(BN(h)) ------------------------------------
__global__ void k_out(const float* __restrict__ x, float* __restrict__ out) {
    int i = blockIdx.x * blockDim.x + threadIdx.x;
    const int total = N_NODES * OUT_C / 4;
    if (i < total) {
        float4 xv = ((const float4*)x)[i];
        float4 hv = ((const float4*)g_h)[i];
        int c = (i & 7) * 4;
        float4 o;
        o.x = xv.x + fmaxf(hv.x * g_scale[c + 0] + g_shift[c + 0], 0.f);
        o.y = xv.y + fmaxf(hv.y * g_scale[c + 1] + g_shift[c + 1], 0.f);
        o.z = xv.z + fmaxf(hv.z * g_scale[c + 2] + g_shift[c + 2], 0.f);
        o.w = xv.w + fmaxf(hv.w * g_scale[c + 3] + g_shift[c + 3], 0.f);
        ((float4*)out)[i] = o;
    }
}

// ---------------- launch -----------------------------------------------------
extern "C" void kernel_launch(void* const* d_in, const int* in_sizes, int n_in,
                              void* d_out, int out_size) {
    const float* x   = (const float*)d_in[0];
    const void*  ei  = d_in[1];               // int32 or int64, detected on device
    const float* ea  = (const float*)d_in[2];
    const float* w1  = (const float*)d_in[3];
    const float* b1  = (const float*)d_in[4];
    const float* w2  = (const float*)d_in[5];
    const float* b2  = (const float*)d_in[6];
    const float* rw  = (const float*)d_in[7];
    const float* cb  = (const float*)d_in[8];
    const float* gam = (const float*)d_in[9];
    const float* bet = (const float*)d_in[10];
    float* out = (float*)d_out;

    k_detect<<<1, 32>>>(ei);
    k_init<<<196, 256>>>();
    k_hist<<<512, 256>>>(ei);
    k_scan_a<<<SCAN_BLOCKS, 256>>>();
    k_scan_b<<<1, 256>>>();
    k_scan_c<<<SCAN_BLOCKS, 256>>>();
    k_scatter<<<512, 256>>>(ei);
    k_edgemlp<<<N_EDGES / 32, 128>>>(ea, w1, b1);
    k_abuild<<<N_NODES, 128>>>(x, ei);
    k_gemm<<<(N_NODES + BM - 1) / BM, 256>>>(x, w2, b2, rw, cb);
    k_bnstats<<<BN_BLOCKS, 256>>>();
    k_bnfin<<<1, 32>>>(gam, bet);
    k_out<<<(N_NODES * OUT_C / 4 + 255) / 256, 256>>>(x, out);
}

// round 4
// speedup vs baseline: 1.2913x; 1.0458x over previous
#include <cuda_runtime.h>
#include <cuda_bf16.h>
#include <cstdint>

#define N_NODES 50000
#define N_EDGES 400000
#define IN_C 32
#define OUT_C 32
#define EDGE_DIM 16
#define HIDDEN 128
#define BN_EPS 1e-5f

#define A_COLS (HIDDEN * IN_C)   // 4096
#define SCAN_BLOCKS ((N_NODES + 255) / 256)  // 196
#define BN_BLOCKS 232

// GEMM tiling
#define BM 128
#define BK 32
#define NKT (A_COLS / BK)  // 128
#define ASTR 40   // bf16 row stride: conflict-free mma fragment LDS
#define WSTR 40

// abuild chunking
#define EDGE_CHUNK 256

// ---------------- static device scratch (no allocations allowed) ------------
__device__ float g_A[(size_t)N_NODES * A_COLS];        // 819 MB
__device__ float g_xsum[(size_t)N_NODES * IN_C];
__device__ float g_h[(size_t)N_NODES * OUT_C];
__device__ int   g_hist[N_NODES];
__device__ int   g_off[N_NODES + 1];
__device__ int   g_cursor[N_NODES];
__device__ int   g_perm[N_EDGES];
__device__ int   g_bsum[256];
__device__ int   g_boff[256];
__device__ double g_psum[BN_BLOCKS][OUT_C];
__device__ double g_psq[BN_BLOCKS][OUT_C];
__device__ float g_scale[OUT_C];
__device__ float g_shift[OUT_C];
__device__ int   g_is64;

// ---------------- init + edge_index dtype detection --------------------------
__global__ void k_init(const void* ei) {
    if (blockIdx.x == 0 && threadIdx.x == 0) {
        const int* p = (const int*)ei;
        int is64 = 1;
        for (int i = 0; i < 512; i++)
            if (p[2 * i + 1] != 0) { is64 = 0; break; }
        g_is64 = is64;
    }
    for (int i = blockIdx.x * blockDim.x + threadIdx.x; i < N_NODES;
         i += gridDim.x * blockDim.x)
        g_hist[i] = 0;
}

__device__ __forceinline__ int load_idx(const void* ei, int is64, long long elem) {
    int v = is64 ? (int)((const long long*)ei)[elem] : ((const int*)ei)[elem];
    return min(max(v, 0), N_NODES - 1);
}

// ---------------- histogram over dst ----------------------------------------
__global__ void k_hist(const void* __restrict__ ei) {
    int is64 = g_is64;
    for (int i = blockIdx.x * blockDim.x + threadIdx.x; i < N_EDGES;
         i += gridDim.x * blockDim.x) {
        int dst = load_idx(ei, is64, (long long)N_EDGES + i);
        atomicAdd(&g_hist[dst], 1);
    }
}

// ---------------- 3-kernel exclusive scan (256/block) -----------------------
__device__ __forceinline__ int block_excl_scan256(int v) {
    int tid = threadIdx.x;
    int lane = tid & 31, wid = tid >> 5;
    int incl = v;
#pragma unroll
    for (int o = 1; o < 32; o <<= 1) {
        int nv = __shfl_up_sync(0xffffffffu, incl, o);
        if (lane >= o) incl += nv;
    }
    __shared__ int ws[8];
    if (lane == 31) ws[wid] = incl;
    __syncthreads();
    if (wid == 0) {
        int wv = (lane < 8) ? ws[lane] : 0;
#pragma unroll
        for (int o = 1; o < 8; o <<= 1) {
            int nv = __shfl_up_sync(0xffffffffu, wv, o);
            if (lane >= o) wv += nv;
        }
        if (lane < 8) ws[lane] = wv;
    }
    __syncthreads();
    int base = (wid > 0) ? ws[wid - 1] : 0;
    return base + incl - v;
}

__global__ void k_scan_a() {
    int idx = blockIdx.x * 256 + threadIdx.x;
    int v = (idx < N_NODES) ? g_hist[idx] : 0;
    int ex = block_excl_scan256(v);
    if (threadIdx.x == 255) g_bsum[blockIdx.x] = ex + v;
}

__global__ void k_scan_b() {
    int tid = threadIdx.x;
    int v = (tid < SCAN_BLOCKS) ? g_bsum[tid] : 0;
    int ex = block_excl_scan256(v);
    if (tid < SCAN_BLOCKS) g_boff[tid] = ex;
    if (tid == 0) g_off[N_NODES] = N_EDGES;
}

__global__ void k_scan_c() {
    int idx = blockIdx.x * 256 + threadIdx.x;
    int v = (idx < N_NODES) ? g_hist[idx] : 0;
    int ex = block_excl_scan256(v) + g_boff[blockIdx.x];
    if (idx < N_NODES) {
        g_off[idx] = ex;
        g_cursor[idx] = ex;
    }
}

// ---------------- scatter edge ids grouped by dst ---------------------------
__global__ void k_scatter(const void* __restrict__ ei) {
    int is64 = g_is64;
    for (int i = blockIdx.x * blockDim.x + threadIdx.x; i < N_EDGES;
         i += gridDim.x * blockDim.x) {
        int dst = load_idx(ei, is64, (long long)N_EDGES + i);
        int pos = atomicAdd(&g_cursor[dst], 1);
        g_perm[pos] = i;
    }
}

// ---------------- A build with fused edge MLP --------------------------------
// block = one node, 128 threads (h = tid). Per edge: recompute
// H[e,tid] = relu(ea[e]·w1[:,tid]+b1[tid]) from smem-staged ea, then rank-1
// accumulate with gathered x[src].
__global__ void __launch_bounds__(128) k_abuild(const float* __restrict__ x,
                                                const void* __restrict__ ei,
                                                const float* __restrict__ ea,
                                                const float* __restrict__ w1,
                                                const float* __restrict__ b1) {
    int n = blockIdx.x;
    int tid = threadIdx.x;
    int is64 = g_is64;
    int start = g_off[n], end = g_off[n + 1];
    int d = end - start;

    float w1r[EDGE_DIM];
#pragma unroll
    for (int k = 0; k < EDGE_DIM; k++) w1r[k] = w1[k * HIDDEN + tid];
    float b1v = b1[tid];

    __shared__ int s_src[EDGE_CHUNK];
    __shared__ int s_e[EDGE_CHUNK];
    __shared__ float4 s_ea[EDGE_CHUNK][4];

    float acc[IN_C];
#pragma unroll
    for (int i = 0; i < IN_C; i++) acc[i] = 0.f;
    float xs = 0.f;

    for (int base = 0; base < d; base += EDGE_CHUNK) {
        int cnt = min(d - base, EDGE_CHUNK);
        __syncthreads();
        // phase 1: edge ids + sources
        for (int j = tid; j < cnt; j += 128) {
            int e = g_perm[start + base + j];
            s_e[j] = e;
            s_src[j] = load_idx(ei, is64, e);
        }
        __syncthreads();
        // phase 2: edge attributes
        for (int idx = tid; idx < cnt * 4; idx += 128) {
            int j = idx >> 2, q = idx & 3;
            s_ea[j][q] = ((const float4*)(ea + (size_t)s_e[j] * EDGE_DIM))[q];
        }
        __syncthreads();
        // phase 3: serial accumulate
        for (int j = 0; j < cnt; j++) {
            int src = s_src[j];
            const float4* xp = (const float4*)(x + (size_t)src * IN_C);
            float4 xv[8];
#pragma unroll
            for (int q = 0; q < 8; q++) xv[q] = xp[q];   // broadcast LDGs in flight
            float xsv = (tid < IN_C) ? x[(size_t)src * IN_C + tid] : 0.f;

            float4 e0 = s_ea[j][0], e1 = s_ea[j][1], e2 = s_ea[j][2],
                   e3 = s_ea[j][3];
            float he = b1v;
            he += e0.x * w1r[0] + e0.y * w1r[1] + e0.z * w1r[2] + e0.w * w1r[3];
            he += e1.x * w1r[4] + e1.y * w1r[5] + e1.z * w1r[6] + e1.w * w1r[7];
            he += e2.x * w1r[8] + e2.y * w1r[9] + e2.z * w1r[10] + e2.w * w1r[11];
            he += e3.x * w1r[12] + e3.y * w1r[13] + e3.z * w1r[14] + e3.w * w1r[15];
            he = fmaxf(he, 0.f);

#pragma unroll
            for (int q = 0; q < 8; q++) {
                acc[4 * q + 0] += he * xv[q].x;
                acc[4 * q + 1] += he * xv[q].y;
                acc[4 * q + 2] += he * xv[q].z;
                acc[4 * q + 3] += he * xv[q].w;
            }
            xs += xsv;
        }
    }

    float4* ap = (float4*)(g_A + (size_t)n * A_COLS + tid * IN_C);
#pragma unroll
    for (int q = 0; q < 8; q++)
        ap[q] = make_float4(acc[4 * q + 0], acc[4 * q + 1], acc[4 * q + 2],
                            acc[4 * q + 3]);
    if (tid < IN_C) g_xsum[n * IN_C + tid] = xs;
}

// ---------------- helpers for split-bf16 MMA ---------------------------------
__device__ __forceinline__ void split_bf(float v, __nv_bfloat16& h,
                                         __nv_bfloat16& l) {
    h = __float2bfloat16_rn(v);
    l = __float2bfloat16_rn(v - __bfloat162float(h));
}

__device__ __forceinline__ uint32_t pack_bf(__nv_bfloat16 a, __nv_bfloat16 b) {
    __nv_bfloat162 p;
    p.x = a; p.y = b;
    return *reinterpret_cast<uint32_t*>(&p);
}

__device__ __forceinline__ uint32_t lds_u32(const __nv_bfloat16* p) {
    return *reinterpret_cast<const uint32_t*>(p);
}

__device__ __forceinline__ void mma16816(float c[4], uint32_t a0, uint32_t a1,
                                         uint32_t a2, uint32_t a3, uint32_t b0,
                                         uint32_t b1) {
    asm volatile(
        "mma.sync.aligned.m16n8k16.row.col.f32.bf16.bf16.f32 "
        "{%0,%1,%2,%3}, {%4,%5,%6,%7}, {%8,%9}, {%0,%1,%2,%3};"
        : "+f"(c[0]), "+f"(c[1]), "+f"(c[2]), "+f"(c[3])
        : "r"(a0), "r"(a1), "r"(a2), "r"(a3), "r"(b0), "r"(b1));
}

// ---------------- main GEMM on tensor cores (split bf16, 3 passes) ----------
// Software-pipelined: LDG for kt+1 issued before MMAs of kt.
__global__ void __launch_bounds__(256) k_gemm(const float* __restrict__ x,
                                              const float* __restrict__ w2,
                                              const float* __restrict__ b2,
                                              const float* __restrict__ rw,
                                              const float* __restrict__ cb) {
    __shared__ __align__(16) unsigned char SMEM[25600];
    __nv_bfloat16* A_hi = (__nv_bfloat16*)SMEM;                    // 10240 B
    __nv_bfloat16* A_lo = (__nv_bfloat16*)(SMEM + 10240);          // 10240 B
    __nv_bfloat16* Wt_hi = (__nv_bfloat16*)(SMEM + 20480);         // 2560 B
    __nv_bfloat16* Wt_lo = (__nv_bfloat16*)(SMEM + 23040);         // 2560 B
    float* C_s = (float*)SMEM;  // 16 KB alias, used after the mainloop
    __shared__ float B2s[1024], RWs[1024], cbs[32];

    int tid = threadIdx.x;
    int warp = tid >> 5, lane = tid & 31;
    int gi = lane >> 2, tq = lane & 3;
    int rowbase = blockIdx.x * BM;

#pragma unroll
    for (int q = 0; q < 4; q++) {
        int id = tid + q * 256;
        B2s[id] = b2[id];
        RWs[id] = rw[id];
    }
    if (tid < 32) cbs[tid] = cb[tid];

    float c[4][4];
#pragma unroll
    for (int j = 0; j < 4; j++)
#pragma unroll
        for (int r = 0; r < 4; r++) c[j][r] = 0.f;

    int lrow = tid >> 1, half = tid & 1;
    bool rowok = (rowbase + lrow) < N_NODES;
    const float4* asrc =
        (const float4*)(g_A + (size_t)(rowbase + lrow) * A_COLS) + half * 4;

    float4 va[4];
    float wv[4];

    // ---- prologue: load + store kt = 0 ----
#pragma unroll
    for (int q = 0; q < 4; q++)
        va[q] = rowok ? asrc[q] : make_float4(0.f, 0.f, 0.f, 0.f);
#pragma unroll
    for (int q = 0; q < 4; q++) {
        int id = tid + q * 256;
        wv[q] = w2[(size_t)(id >> 5) * 32 + (id & 31)];
    }
    {
#pragma unroll
        for (int q = 0; q < 4; q++) {
            int scol = half * 16 + q * 4;
            __nv_bfloat16 h0, h1, h2, h3, l0, l1, l2, l3;
            split_bf(va[q].x, h0, l0); split_bf(va[q].y, h1, l1);
            split_bf(va[q].z, h2, l2); split_bf(va[q].w, h3, l3);
            uint32_t* dh = (uint32_t*)&A_hi[lrow * ASTR + scol];
            uint32_t* dl = (uint32_t*)&A_lo[lrow * ASTR + scol];
            dh[0] = pack_bf(h0, h1); dh[1] = pack_bf(h2, h3);
            dl[0] = pack_bf(l0, l1); dl[1] = pack_bf(l2, l3);
        }
#pragma unroll
        for (int q = 0; q < 4; q++) {
            int id = tid + q * 256;
            int k = id >> 5, nn = id & 31;
            __nv_bfloat16 wh, wl;
            split_bf(wv[q], wh, wl);
            Wt_hi[nn * WSTR + k] = wh;
            Wt_lo[nn * WSTR + k] = wl;
        }
    }
    __syncthreads();

    for (int kt = 0; kt < NKT; kt++) {
        // ---- prefetch kt+1 into registers (overlaps the MMAs below) ----
        int ktn = (kt + 1 < NKT) ? kt + 1 : kt;
#pragma unroll
        for (int q = 0; q < 4; q++)
            va[q] = rowok ? asrc[ktn * 8 + q] : make_float4(0.f, 0.f, 0.f, 0.f);
#pragma unroll
        for (int q = 0; q < 4; q++) {
            int id = tid + q * 256;
            wv[q] = w2[(size_t)(ktn * BK + (id >> 5)) * 32 + (id & 31)];
        }

        // ---- MMAs for kt from smem ----
        int rb = warp * 16;
#pragma unroll
        for (int kk = 0; kk < BK; kk += 16) {
            const __nv_bfloat16* ah = &A_hi[(rb + gi) * ASTR + kk + 2 * tq];
            const __nv_bfloat16* al = &A_lo[(rb + gi) * ASTR + kk + 2 * tq];
            uint32_t a0h = lds_u32(ah), a1h = lds_u32(ah + 8 * ASTR);
            uint32_t a2h = lds_u32(ah + 8), a3h = lds_u32(ah + 8 * ASTR + 8);
            uint32_t a0l = lds_u32(al), a1l = lds_u32(al + 8 * ASTR);
            uint32_t a2l = lds_u32(al + 8), a3l = lds_u32(al + 8 * ASTR + 8);
#pragma unroll
            for (int j = 0; j < 4; j++) {
                const __nv_bfloat16* bh = &Wt_hi[(j * 8 + gi) * WSTR + kk + 2 * tq];
                const __nv_bfloat16* bl = &Wt_lo[(j * 8 + gi) * WSTR + kk + 2 * tq];
                uint32_t b0h = lds_u32(bh), b1h = lds_u32(bh + 8);
                uint32_t b0l = lds_u32(bl), b1l = lds_u32(bl + 8);
                mma16816(c[j], a0h, a1h, a2h, a3h, b0h, b1h);
                mma16816(c[j], a0h, a1h, a2h, a3h, b0l, b1l);
                mma16816(c[j], a0l, a1l, a2l, a3l, b0h, b1h);
            }
        }
        __syncthreads();   // all reads of smem tiles done

        if (kt + 1 < NKT) {
#pragma unroll
            for (int q = 0; q < 4; q++) {
                int scol = half * 16 + q * 4;
                __nv_bfloat16 h0, h1, h2, h3, l0, l1, l2, l3;
                split_bf(va[q].x, h0, l0); split_bf(va[q].y, h1, l1);
                split_bf(va[q].z, h2, l2); split_bf(va[q].w, h3, l3);
                uint32_t* dh = (uint32_t*)&A_hi[lrow * ASTR + scol];
                uint32_t* dl = (uint32_t*)&A_lo[lrow * ASTR + scol];
                dh[0] = pack_bf(h0, h1); dh[1] = pack_bf(h2, h3);
                dl[0] = pack_bf(l0, l1); dl[1] = pack_bf(l2, l3);
            }
#pragma unroll
            for (int q = 0; q < 4; q++) {
                int id = tid + q * 256;
                int k = id >> 5, nn = id & 31;
                __nv_bfloat16 wh, wl;
                split_bf(wv[q], wh, wl);
                Wt_hi[nn * WSTR + k] = wh;
                Wt_lo[nn * WSTR + k] = wl;
            }
        }
        __syncthreads();   // smem tiles (kt+1) visible
    }

    // ---- dump accumulators to shared (aliases A planes) ----
    {
        int rb = warp * 16;
#pragma unroll
        for (int j = 0; j < 4; j++) {
            int col = j * 8 + 2 * tq;
            C_s[(rb + gi) * 32 + col] = c[j][0];
            C_s[(rb + gi) * 32 + col + 1] = c[j][1];
            C_s[(rb + gi + 8) * 32 + col] = c[j][2];
            C_s[(rb + gi + 8) * 32 + col + 1] = c[j][3];
        }
    }
    __syncthreads();

    // ---- epilogue: mean, b2 term, root term, conv bias ----
    {
        int row = tid >> 1, ch = tid & 1;
        int mg = rowbase + row;
        if (mg < N_NODES) {
            float cnt = (float)(g_off[mg + 1] - g_off[mg]);
            float inv = 1.f / fmaxf(cnt, 1.f);
            const float4* xsp = (const float4*)(g_xsum + (size_t)mg * IN_C);
            const float4* xp = (const float4*)(x + (size_t)mg * IN_C);
            float eacc[16], racc[16];
#pragma unroll
            for (int cjj = 0; cjj < 16; cjj++) { eacc[cjj] = 0.f; racc[cjj] = 0.f; }
#pragma unroll
            for (int i4 = 0; i4 < 8; i4++) {
                float4 xsv = xsp[i4];
                float4 xvv = xp[i4];
                float sv[4] = {xsv.x, xsv.y, xsv.z, xsv.w};
                float vv[4] = {xvv.x, xvv.y, xvv.z, xvv.w};
#pragma unroll
                for (int ii = 0; ii < 4; ii++) {
                    int i = i4 * 4 + ii;
#pragma unroll
                    for (int cjj = 0; cjj < 16; cjj++) {
                        int col = ch * 16 + cjj;
                        eacc[cjj] += sv[ii] * B2s[i * 32 + col];
                        racc[cjj] += vv[ii] * RWs[i * 32 + col];
                    }
                }
            }
#pragma unroll
            for (int cjj = 0; cjj < 16; cjj++) {
                int col = ch * 16 + cjj;
                g_h[(size_t)mg * 32 + col] =
                    (C_s[row * 32 + col] + eacc[cjj]) * inv + racc[cjj] + cbs[col];
            }
        }
    }
}

// ---------------- BatchNorm statistics (deterministic, no atomics) ----------
__global__ void k_bnstats() {
    int tid = threadIdx.x;  // 256
    int c = tid & 31, g = tid >> 5;
    double s = 0.0, s2 = 0.0;
    for (int row = blockIdx.x * 8 + g; row < N_NODES; row += gridDim.x * 8) {
        float v = g_h[(size_t)row * 32 + c];
        s += (double)v;
        s2 += (double)v * (double)v;
    }
    __shared__ double sh[256], sh2[256];
    sh[tid] = s; sh2[tid] = s2;
    __syncthreads();
    for (int off = 128; off >= 32; off >>= 1) {
        if (tid < off) { sh[tid] += sh[tid + off]; sh2[tid] += sh2[tid + off]; }
        __syncthreads();
    }
    if (tid < 32) {
        g_psum[blockIdx.x][tid] = sh[tid];
        g_psq[blockIdx.x][tid] = sh2[tid];
    }
}

__global__ void k_bnfin(const float* __restrict__ gamma,
                        const float* __restrict__ beta) {
    int c = threadIdx.x;
    if (c < OUT_C) {
        double s = 0.0, s2 = 0.0;
        for (int b = 0; b < BN_BLOCKS; b++) {
            s += g_psum[b][c];
            s2 += g_psq[b][c];
        }
        double mu = s / (double)N_NODES;
        double var = s2 / (double)N_NODES - mu * mu;
        float rstd = (float)rsqrt(var + (double)BN_EPS);
        float sc = rstd * gamma[c];
        g_scale[c] = sc;
        g_shift[c] = beta[c] - (float)mu * sc;
    }
}

// ---------------- output: x + relu(BN(h)) ------------------------------------
__global__ void k_out(const float* __restrict__ x, float* __restrict__ out) {
    int i = blockIdx.x * blockDim.x + threadIdx.x;
    const int total = N_NODES * OUT_C / 4;
    if (i < total) {
        float4 xv = ((const float4*)x)[i];
        float4 hv = ((const float4*)g_h)[i];
        int c = (i & 7) * 4;
        float4 o;
        o.x = xv.x + fmaxf(hv.x * g_scale[c + 0] + g_shift[c + 0], 0.f);
        o.y = xv.y + fmaxf(hv.y * g_scale[c + 1] + g_shift[c + 1], 0.f);
        o.z = xv.z + fmaxf(hv.z * g_scale[c + 2] + g_shift[c + 2], 0.f);
        o.w = xv.w + fmaxf(hv.w * g_scale[c + 3] + g_shift[c + 3], 0.f);
        ((float4*)out)[i] = o;
    }
}

// ---------------- launch -----------------------------------------------------
extern "C" void kernel_launch(void* const* d_in, const int* in_sizes, int n_in,
                              void* d_out, int out_size) {
    const float* x   = (const float*)d_in[0];
    const void*  ei  = d_in[1];               // int32 or int64, detected on device
    const float* ea  = (const float*)d_in[2];
    const float* w1  = (const float*)d_in[3];
    const float* b1  = (const float*)d_in[4];
    const float* w2  = (const float*)d_in[5];
    const float* b2  = (const float*)d_in[6];
    const float* rw  = (const float*)d_in[7];
    const float* cb  = (const float*)d_in[8];
    const float* gam = (const float*)d_in[9];
    const float* bet = (const float*)d_in[10];
    float* out = (float*)d_out;

    k_init<<<196, 256>>>(ei);
    k_hist<<<512, 256>>>(ei);
    k_scan_a<<<SCAN_BLOCKS, 256>>>();
    k_scan_b<<<1, 256>>>();
    k_scan_c<<<SCAN_BLOCKS, 256>>>();
    k_scatter<<<512, 256>>>(ei);
    k_abuild<<<N_NODES, 128>>>(x, ei, ea, w1, b1);
    k_gemm<<<(N_NODES + BM - 1) / BM, 256>>>(x, w2, b2, rw, cb);
    k_bnstats<<<BN_BLOCKS, 256>>>();
    k_bnfin<<<1, 32>>>(gam, bet);
    k_out<<<(N_NODES * OUT_C / 4 + 255) / 256, 256>>>(x, out);
}